// round 8
// baseline (speedup 1.0000x reference)
#include <cuda_runtime.h>
#include <cuda_bf16.h>
#include <math.h>
#include <stdint.h>
#include <string.h>

#define D_MODEL 1024
#define NTOK    8192   // B*T
#define HEADS   16
#define HD      64
#define TSEQ    2048
#define BATCH   4

// GEMM tiling
#define BM 128
#define BN 128
#define BKT 16
#define APAD 20
#define BPAD 136

// Attention bf16 smem pitch (bf16 elements). 72*2B=144B rows; 36 words.
#define PB   72
#define PB32 36

// Scratch (no allocation allowed — device globals). 16B-aligned.
__device__ __align__(16) float g_Q[NTOK * D_MODEL];
__device__ __align__(16) float g_K[NTOK * D_MODEL];
__device__ __align__(16) float g_V[NTOK * D_MODEL];
__device__ __align__(16) float g_A[NTOK * D_MODEL];

__device__ __forceinline__ float tf32r(float x) {
    uint32_t u;
    asm("cvt.rna.tf32.f32 %0, %1;" : "=r"(u) : "f"(x));
    return __uint_as_float(u);
}

__device__ __forceinline__ void mma_tf32(float* c, const uint32_t* a, const uint32_t* b) {
    asm volatile(
        "mma.sync.aligned.m16n8k8.row.col.f32.tf32.tf32.f32 "
        "{%0,%1,%2,%3}, {%4,%5,%6,%7}, {%8,%9}, {%0,%1,%2,%3};\n"
        : "+f"(c[0]), "+f"(c[1]), "+f"(c[2]), "+f"(c[3])
        : "r"(a[0]), "r"(a[1]), "r"(a[2]), "r"(a[3]), "r"(b[0]), "r"(b[1]));
}

__device__ __forceinline__ void mma_bf16(float* c, const uint32_t* a, uint32_t b0, uint32_t b1) {
    asm volatile(
        "mma.sync.aligned.m16n8k16.row.col.f32.bf16.bf16.f32 "
        "{%0,%1,%2,%3}, {%4,%5,%6,%7}, {%8,%9}, {%0,%1,%2,%3};\n"
        : "+f"(c[0]), "+f"(c[1]), "+f"(c[2]), "+f"(c[3])
        : "r"(a[0]), "r"(a[1]), "r"(a[2]), "r"(a[3]), "r"(b0), "r"(b1));
}

// ldmatrix x4: four 8x8 bf16 matrices, lane-group i supplies rows of matrix i
__device__ __forceinline__ void ldsm_x4(uint32_t& r0, uint32_t& r1,
                                        uint32_t& r2, uint32_t& r3, uint32_t addr) {
    asm volatile("ldmatrix.sync.aligned.m8n8.x4.shared.b16 {%0,%1,%2,%3}, [%4];"
                 : "=r"(r0), "=r"(r1), "=r"(r2), "=r"(r3) : "r"(addr));
}

__device__ __forceinline__ uint32_t cvta_smem(const void* p) {
    return (uint32_t)__cvta_generic_to_shared(p);
}

// split fp32 -> bf16 hi + bf16 lo  (hi+lo reproduces ~16 mantissa bits)
__device__ __forceinline__ void bsplit(float x, __nv_bfloat16& h, __nv_bfloat16& l) {
    h = __float2bfloat16(x);
    l = __float2bfloat16(x - __bfloat162float(h));
}

// pack two bf16 into one 32-bit word
__device__ __forceinline__ uint32_t pack2(__nv_bfloat16 lo, __nv_bfloat16 hi) {
    __nv_bfloat162 p = __halves2bfloat162(lo, hi);
    uint32_t u;
    memcpy(&u, &p, 4);
    return u;
}

// ---------------------------------------------------------------------------
// TF32 tensor-core GEMM (unchanged from passing R7 kernel)
// ---------------------------------------------------------------------------
__global__ __launch_bounds__(256, 2)
void gemm_tf32_bias(const float* __restrict__ A, const float* __restrict__ B,
                    const float* __restrict__ bias, float* __restrict__ C,
                    int M, int N, int K)
{
    __shared__ float As[BM * APAD];
    __shared__ float Bs[BKT * BPAD];

    const int tid  = threadIdx.x;
    const int warp = tid >> 5, lane = tid & 31;
    const int g = lane >> 2, t = lane & 3;
    const int wm = (warp >> 2) * 64;
    const int wn = (warp & 3) * 32;

    const int bx = blockIdx.x, by = blockIdx.y;
    const float* Ab = A + (size_t)by * BM * K;
    const float* Bb = B + bx * BN;

    const int arow = tid >> 1, acol = (tid & 1) * 8;
    const int brow = tid >> 4, bcol = (tid & 15) * 8;

    float4 pa0 = *(const float4*)(Ab + (size_t)arow * K + acol);
    float4 pa1 = *(const float4*)(Ab + (size_t)arow * K + acol + 4);
    float4 pb0 = *(const float4*)(Bb + (size_t)brow * N + bcol);
    float4 pb1 = *(const float4*)(Bb + (size_t)brow * N + bcol + 4);

    float acc[4][4][4];
#pragma unroll
    for (int mt = 0; mt < 4; mt++)
#pragma unroll
        for (int nt = 0; nt < 4; nt++)
#pragma unroll
            for (int i = 0; i < 4; i++) acc[mt][nt][i] = 0.f;

    for (int k0 = 0; k0 < K; k0 += BKT) {
        float* ad = As + arow * APAD + acol;
        ad[0] = tf32r(pa0.x); ad[1] = tf32r(pa0.y); ad[2] = tf32r(pa0.z); ad[3] = tf32r(pa0.w);
        ad[4] = tf32r(pa1.x); ad[5] = tf32r(pa1.y); ad[6] = tf32r(pa1.z); ad[7] = tf32r(pa1.w);
        float* bd = Bs + brow * BPAD + bcol;
        bd[0] = tf32r(pb0.x); bd[1] = tf32r(pb0.y); bd[2] = tf32r(pb0.z); bd[3] = tf32r(pb0.w);
        bd[4] = tf32r(pb1.x); bd[5] = tf32r(pb1.y); bd[6] = tf32r(pb1.z); bd[7] = tf32r(pb1.w);
        __syncthreads();

        if (k0 + BKT < K) {
            pa0 = *(const float4*)(Ab + (size_t)arow * K + k0 + BKT + acol);
            pa1 = *(const float4*)(Ab + (size_t)arow * K + k0 + BKT + acol + 4);
            pb0 = *(const float4*)(Bb + (size_t)(k0 + BKT + brow) * N + bcol);
            pb1 = *(const float4*)(Bb + (size_t)(k0 + BKT + brow) * N + bcol + 4);
        }

#pragma unroll
        for (int kk = 0; kk < BKT; kk += 8) {
            uint32_t af[4][4];
#pragma unroll
            for (int mt = 0; mt < 4; mt++) {
                const float* ap = As + (wm + mt * 16 + g) * APAD + kk + t;
                af[mt][0] = __float_as_uint(ap[0]);
                af[mt][1] = __float_as_uint(ap[8 * APAD]);
                af[mt][2] = __float_as_uint(ap[4]);
                af[mt][3] = __float_as_uint(ap[8 * APAD + 4]);
            }
            uint32_t bf[4][2];
#pragma unroll
            for (int nt = 0; nt < 4; nt++) {
                const float* bp = Bs + (kk + t) * BPAD + wn + nt * 8 + g;
                bf[nt][0] = __float_as_uint(bp[0]);
                bf[nt][1] = __float_as_uint(bp[4 * BPAD]);
            }
#pragma unroll
            for (int mt = 0; mt < 4; mt++)
#pragma unroll
                for (int nt = 0; nt < 4; nt++)
                    mma_tf32(acc[mt][nt], af[mt], bf[nt]);
        }
        __syncthreads();
    }

#pragma unroll
    for (int mt = 0; mt < 4; mt++) {
        int row0 = by * BM + wm + mt * 16 + g;
#pragma unroll
        for (int nt = 0; nt < 4; nt++) {
            int col = bx * BN + wn + nt * 8 + 2 * t;
            float b0 = bias[col], b1 = bias[col + 1];
            float2 r0 = make_float2(acc[mt][nt][0] + b0, acc[mt][nt][1] + b1);
            float2 r1 = make_float2(acc[mt][nt][2] + b0, acc[mt][nt][3] + b1);
            *(float2*)(C + (size_t)row0 * N + col) = r0;
            *(float2*)(C + (size_t)(row0 + 8) * N + col) = r1;
        }
    }
}

// ---------------------------------------------------------------------------
// Flash attention, bf16x3 split MMA. P in registers, Q fragments hoisted,
// K/V fragments via ldmatrix.x4 (4 words/instr, conflict-free at pitch 72).
// smem planes (pitch PB=72 bf16): Qh Ql Kh Kl Vth Vtl = 55296 B.
// ---------------------------------------------------------------------------
#define OFF_QH 0
#define OFF_QL (64 * PB)
#define OFF_KH (2 * 64 * PB)
#define OFF_KL (3 * 64 * PB)
#define OFF_VH (4 * 64 * PB)
#define OFF_VL (5 * 64 * PB)
#define ATT_SMEM (6 * 64 * PB * 2)   // 55296 bytes

__global__ __launch_bounds__(128, 3)
void attention_bf16x3_kernel(const float* __restrict__ Q, const float* __restrict__ K,
                             const float* __restrict__ V, float* __restrict__ O)
{
    extern __shared__ __align__(16) __nv_bfloat16 sb[];
    __nv_bfloat16* Qh = sb + OFF_QH;
    __nv_bfloat16* Ql = sb + OFF_QL;
    __nv_bfloat16* Kh = sb + OFF_KH;
    __nv_bfloat16* Kl = sb + OFF_KL;
    __nv_bfloat16* Vh = sb + OFF_VH;   // transposed [d][key]
    __nv_bfloat16* Vl = sb + OFF_VL;

    const uint32_t* Qh32 = (const uint32_t*)Qh;
    const uint32_t* Ql32 = (const uint32_t*)Ql;

    const int tid  = threadIdx.x;
    const int warp = tid >> 5, lane = tid & 31;
    const int g = lane >> 2, t = lane & 3;
    const int row16 = warp * 16;

    // ldmatrix lane mapping: group (which 8x8 matrix) and row within it
    const int lgrp = lane >> 3, lrow = lane & 7;
    const uint32_t lm_off = (uint32_t)(lrow * PB + lgrp * 8) * 2;  // bytes
    const uint32_t kh_base = cvta_smem(Kh) + lm_off;
    const uint32_t kl_base = cvta_smem(Kl) + lm_off;
    const uint32_t vh_base = cvta_smem(Vh) + lm_off;
    const uint32_t vl_base = cvta_smem(Vl) + lm_off;

    const int qt = blockIdx.x, h = blockIdx.y, b = blockIdx.z;
    const size_t base = ((size_t)b * TSEQ) * D_MODEL + (size_t)h * HD;
    const float* Qb = Q + base + (size_t)qt * 64 * D_MODEL;
    const float* Kb = K + base;
    const float* Vb = V + base;

    // ---- Load + scale + split Q once (64x64) ----
#pragma unroll
    for (int it = 0; it < 8; it++) {
        int i = tid + it * 128;
        int r = i >> 4, c = (i & 15) * 4;
        float4 q4 = *(const float4*)(Qb + (size_t)r * D_MODEL + c);
        __nv_bfloat16 h0, h1, h2, h3, l0, l1, l2, l3;
        bsplit(q4.x * 0.125f, h0, l0); bsplit(q4.y * 0.125f, h1, l1);
        bsplit(q4.z * 0.125f, h2, l2); bsplit(q4.w * 0.125f, h3, l3);
        *(uint32_t*)&Qh[r * PB + c]     = pack2(h0, h1);
        *(uint32_t*)&Qh[r * PB + c + 2] = pack2(h2, h3);
        *(uint32_t*)&Ql[r * PB + c]     = pack2(l0, l1);
        *(uint32_t*)&Ql[r * PB + c + 2] = pack2(l2, l3);
    }
    __syncthreads();

    // ---- Hoist Q fragments to registers (loop-invariant) ----
    uint32_t qfh[4][4], qfl[4][4];
#pragma unroll
    for (int u = 0; u < 4; u++) {
        const int w0 = u * 8 + t;
        qfh[u][0] = Qh32[(row16 + g) * PB32 + w0];
        qfh[u][1] = Qh32[(row16 + g + 8) * PB32 + w0];
        qfh[u][2] = Qh32[(row16 + g) * PB32 + w0 + 4];
        qfh[u][3] = Qh32[(row16 + g + 8) * PB32 + w0 + 4];
        qfl[u][0] = Ql32[(row16 + g) * PB32 + w0];
        qfl[u][1] = Ql32[(row16 + g + 8) * PB32 + w0];
        qfl[u][2] = Ql32[(row16 + g) * PB32 + w0 + 4];
        qfl[u][3] = Ql32[(row16 + g + 8) * PB32 + w0 + 4];
    }

    float oacc[8][4];
#pragma unroll
    for (int j = 0; j < 8; j++)
#pragma unroll
        for (int i = 0; i < 4; i++) oacc[j][i] = 0.f;
    float m0 = -1e30f, m1 = -1e30f, l0s = 0.f, l1s = 0.f;

    // V lane mapping for transpose-store: row = 16*warp + (lane&15)
    const int vrow = row16 + (lane & 15);
    const int vcg  = lane >> 4;

    for (int j0 = 0; j0 < TSEQ; j0 += 64) {
        __syncthreads();  // previous tile's K/V reads complete

        // ---- Load + split K (coalesced), V (transposed) ----
#pragma unroll
        for (int it = 0; it < 8; it++) {
            int i = tid + it * 128;
            int r = i >> 4, c = (i & 15) * 4;
            float4 k4 = *(const float4*)(Kb + (size_t)(j0 + r) * D_MODEL + c);
            __nv_bfloat16 h0, h1, h2, h3, l0, l1, l2, l3;
            bsplit(k4.x, h0, l0); bsplit(k4.y, h1, l1);
            bsplit(k4.z, h2, l2); bsplit(k4.w, h3, l3);
            *(uint32_t*)&Kh[r * PB + c]     = pack2(h0, h1);
            *(uint32_t*)&Kh[r * PB + c + 2] = pack2(h2, h3);
            *(uint32_t*)&Kl[r * PB + c]     = pack2(l0, l1);
            *(uint32_t*)&Kl[r * PB + c + 2] = pack2(l2, l3);
        }
#pragma unroll
        for (int it = 0; it < 8; it++) {
            int c = (vcg + 2 * it) * 4;
            float4 v4 = *(const float4*)(Vb + (size_t)(j0 + vrow) * D_MODEL + c);
            __nv_bfloat16 hh, ll;
            bsplit(v4.x, hh, ll); Vh[(c + 0) * PB + vrow] = hh; Vl[(c + 0) * PB + vrow] = ll;
            bsplit(v4.y, hh, ll); Vh[(c + 1) * PB + vrow] = hh; Vl[(c + 1) * PB + vrow] = ll;
            bsplit(v4.z, hh, ll); Vh[(c + 2) * PB + vrow] = hh; Vl[(c + 2) * PB + vrow] = ll;
            bsplit(v4.w, hh, ll); Vh[(c + 3) * PB + vrow] = hh; Vl[(c + 3) * PB + vrow] = ll;
        }
        __syncthreads();

        // ---- S = Q K^T  (bf16x3: QhKh + QhKl + QlKh) ----
        float sacc[8][4];
#pragma unroll
        for (int j = 0; j < 8; j++)
#pragma unroll
            for (int i = 0; i < 4; i++) sacc[j][i] = 0.f;

#pragma unroll
        for (int j = 0; j < 8; j++) {
            const uint32_t joff = (uint32_t)(j * 8 * PB * 2);
            uint32_t khw[8], klw[8];
            ldsm_x4(khw[0], khw[1], khw[2], khw[3], kh_base + joff);
            ldsm_x4(khw[4], khw[5], khw[6], khw[7], kh_base + joff + 64);
            ldsm_x4(klw[0], klw[1], klw[2], klw[3], kl_base + joff);
            ldsm_x4(klw[4], klw[5], klw[6], klw[7], kl_base + joff + 64);
#pragma unroll
            for (int u = 0; u < 4; u++) {
                mma_bf16(sacc[j], qfh[u], khw[2 * u], khw[2 * u + 1]);
                mma_bf16(sacc[j], qfh[u], klw[2 * u], klw[2 * u + 1]);
                mma_bf16(sacc[j], qfl[u], khw[2 * u], khw[2 * u + 1]);
            }
        }

        // ---- Online softmax on fragments (rows g and g+8) ----
        float mx0 = -1e30f, mx1 = -1e30f;
#pragma unroll
        for (int j = 0; j < 8; j++) {
            mx0 = fmaxf(mx0, fmaxf(sacc[j][0], sacc[j][1]));
            mx1 = fmaxf(mx1, fmaxf(sacc[j][2], sacc[j][3]));
        }
        mx0 = fmaxf(mx0, __shfl_xor_sync(0xffffffffu, mx0, 1));
        mx0 = fmaxf(mx0, __shfl_xor_sync(0xffffffffu, mx0, 2));
        mx1 = fmaxf(mx1, __shfl_xor_sync(0xffffffffu, mx1, 1));
        mx1 = fmaxf(mx1, __shfl_xor_sync(0xffffffffu, mx1, 2));

        float mn0 = fmaxf(m0, mx0), mn1 = fmaxf(m1, mx1);
        float fac0 = __expf(m0 - mn0), fac1 = __expf(m1 - mn1);
        m0 = mn0; m1 = mn1;

        // P packs (registers): A-fragment halves for the PV mma
        uint32_t ph01[8], ph23[8], pl01[8], pl23[8];
        float rs0 = 0.f, rs1 = 0.f;
#pragma unroll
        for (int j = 0; j < 8; j++) {
            float p0 = __expf(sacc[j][0] - mn0);
            float p1 = __expf(sacc[j][1] - mn0);
            float p2 = __expf(sacc[j][2] - mn1);
            float p3 = __expf(sacc[j][3] - mn1);
            rs0 += p0 + p1; rs1 += p2 + p3;
            __nv_bfloat16 h0, h1, h2, h3, q0, q1, q2, q3;
            bsplit(p0, h0, q0); bsplit(p1, h1, q1);
            bsplit(p2, h2, q2); bsplit(p3, h3, q3);
            ph01[j] = pack2(h0, h1);
            ph23[j] = pack2(h2, h3);
            pl01[j] = pack2(q0, q1);
            pl23[j] = pack2(q2, q3);
        }
        rs0 += __shfl_xor_sync(0xffffffffu, rs0, 1);
        rs0 += __shfl_xor_sync(0xffffffffu, rs0, 2);
        rs1 += __shfl_xor_sync(0xffffffffu, rs1, 1);
        rs1 += __shfl_xor_sync(0xffffffffu, rs1, 2);
        l0s = l0s * fac0 + rs0;
        l1s = l1s * fac1 + rs1;
#pragma unroll
        for (int j = 0; j < 8; j++) {
            oacc[j][0] *= fac0; oacc[j][1] *= fac0;
            oacc[j][2] *= fac1; oacc[j][3] *= fac1;
        }

        // ---- O += P V  (bf16x3: PhVh + PhVl + PlVh), P regs, V ldmatrix ----
#pragma unroll
        for (int j = 0; j < 8; j++) {
            const uint32_t joff = (uint32_t)(j * 8 * PB * 2);
            uint32_t vhw[8], vlw[8];
            ldsm_x4(vhw[0], vhw[1], vhw[2], vhw[3], vh_base + joff);
            ldsm_x4(vhw[4], vhw[5], vhw[6], vhw[7], vh_base + joff + 64);
            ldsm_x4(vlw[0], vlw[1], vlw[2], vlw[3], vl_base + joff);
            ldsm_x4(vlw[4], vlw[5], vlw[6], vlw[7], vl_base + joff + 64);
#pragma unroll
            for (int u = 0; u < 4; u++) {
                uint32_t pfh[4] = { ph01[2 * u], ph23[2 * u], ph01[2 * u + 1], ph23[2 * u + 1] };
                uint32_t pfl[4] = { pl01[2 * u], pl23[2 * u], pl01[2 * u + 1], pl23[2 * u + 1] };
                mma_bf16(oacc[j], pfh, vhw[2 * u], vhw[2 * u + 1]);
                mma_bf16(oacc[j], pfh, vlw[2 * u], vlw[2 * u + 1]);
                mma_bf16(oacc[j], pfl, vhw[2 * u], vhw[2 * u + 1]);
            }
        }
    }

    // ---- Epilogue: normalize, store ----
    float inv0 = 1.f / l0s, inv1 = 1.f / l1s;
    float* Ob = O + base + (size_t)qt * 64 * D_MODEL;
#pragma unroll
    for (int j = 0; j < 8; j++) {
        int col = j * 8 + 2 * t;
        *(float2*)(Ob + (size_t)(row16 + g) * D_MODEL + col) =
            make_float2(oacc[j][0] * inv0, oacc[j][1] * inv0);
        *(float2*)(Ob + (size_t)(row16 + g + 8) * D_MODEL + col) =
            make_float2(oacc[j][2] * inv1, oacc[j][3] * inv1);
    }
}

// ---------------------------------------------------------------------------
// Launch. Input order:
// 0:q 1:k 2:v 3:W_q 4:b_q 5:W_k 6:b_k 7:W_v 8:b_v 9:W_o 10:b_o
// ---------------------------------------------------------------------------
extern "C" void kernel_launch(void* const* d_in, const int* in_sizes, int n_in,
                              void* d_out, int out_size)
{
    (void)in_sizes; (void)n_in; (void)out_size;
    const float* q   = (const float*)d_in[0];
    const float* k   = (const float*)d_in[1];
    const float* v   = (const float*)d_in[2];
    const float* W_q = (const float*)d_in[3];
    const float* b_q = (const float*)d_in[4];
    const float* W_k = (const float*)d_in[5];
    const float* b_k = (const float*)d_in[6];
    const float* W_v = (const float*)d_in[7];
    const float* b_v = (const float*)d_in[8];
    const float* W_o = (const float*)d_in[9];
    const float* b_o = (const float*)d_in[10];
    float* out = (float*)d_out;

    float *gQ, *gK, *gV, *gA;
    cudaGetSymbolAddress((void**)&gQ, g_Q);
    cudaGetSymbolAddress((void**)&gK, g_K);
    cudaGetSymbolAddress((void**)&gV, g_V);
    cudaGetSymbolAddress((void**)&gA, g_A);

    dim3 gridP(D_MODEL / BN, NTOK / BM);  // (8, 64)

    gemm_tf32_bias<<<gridP, 256>>>(q, W_q, b_q, gQ, NTOK, D_MODEL, D_MODEL);
    gemm_tf32_bias<<<gridP, 256>>>(k, W_k, b_k, gK, NTOK, D_MODEL, D_MODEL);
    gemm_tf32_bias<<<gridP, 256>>>(v, W_v, b_v, gV, NTOK, D_MODEL, D_MODEL);

    cudaFuncSetAttribute(attention_bf16x3_kernel,
                         cudaFuncAttributeMaxDynamicSharedMemorySize, ATT_SMEM);
    attention_bf16x3_kernel<<<dim3(TSEQ / 64, HEADS, BATCH), 128, ATT_SMEM>>>(gQ, gK, gV, gA);

    gemm_tf32_bias<<<gridP, 256>>>(gA, W_o, b_o, out, NTOK, D_MODEL, D_MODEL);
}

// round 9
// speedup vs baseline: 1.1575x; 1.1575x over previous
#include <cuda_runtime.h>
#include <cuda_bf16.h>
#include <math.h>
#include <stdint.h>
#include <string.h>

#define D_MODEL 1024
#define NTOK    8192   // B*T
#define HEADS   16
#define HD      64
#define TSEQ    2048
#define BATCH   4

// GEMM tiling
#define BM 128
#define BN 128
#define BKT 16
#define APAD 20
#define BPAD 136

// Attention bf16 smem pitch (bf16 elements). 72*2B=144B rows; 36 words.
#define PB   72
#define PB32 36

// Scratch (no allocation allowed — device globals). 16B-aligned.
__device__ __align__(16) float g_Q[NTOK * D_MODEL];
__device__ __align__(16) float g_K[NTOK * D_MODEL];
__device__ __align__(16) float g_V[NTOK * D_MODEL];
__device__ __align__(16) float g_A[NTOK * D_MODEL];

__device__ __forceinline__ float tf32r(float x) {
    uint32_t u;
    asm("cvt.rna.tf32.f32 %0, %1;" : "=r"(u) : "f"(x));
    return __uint_as_float(u);
}

__device__ __forceinline__ void mma_tf32(float* c, const uint32_t* a, const uint32_t* b) {
    asm volatile(
        "mma.sync.aligned.m16n8k8.row.col.f32.tf32.tf32.f32 "
        "{%0,%1,%2,%3}, {%4,%5,%6,%7}, {%8,%9}, {%0,%1,%2,%3};\n"
        : "+f"(c[0]), "+f"(c[1]), "+f"(c[2]), "+f"(c[3])
        : "r"(a[0]), "r"(a[1]), "r"(a[2]), "r"(a[3]), "r"(b[0]), "r"(b[1]));
}

__device__ __forceinline__ void mma_bf16(float* c, const uint32_t* a, uint32_t b0, uint32_t b1) {
    asm volatile(
        "mma.sync.aligned.m16n8k16.row.col.f32.bf16.bf16.f32 "
        "{%0,%1,%2,%3}, {%4,%5,%6,%7}, {%8,%9}, {%0,%1,%2,%3};\n"
        : "+f"(c[0]), "+f"(c[1]), "+f"(c[2]), "+f"(c[3])
        : "r"(a[0]), "r"(a[1]), "r"(a[2]), "r"(a[3]), "r"(b0), "r"(b1));
}

// split fp32 -> bf16 hi + bf16 lo  (hi+lo reproduces ~16 mantissa bits)
__device__ __forceinline__ void bsplit(float x, __nv_bfloat16& h, __nv_bfloat16& l) {
    h = __float2bfloat16(x);
    l = __float2bfloat16(x - __bfloat162float(h));
}

// pack two bf16 into one 32-bit word
__device__ __forceinline__ uint32_t pack2(__nv_bfloat16 lo, __nv_bfloat16 hi) {
    __nv_bfloat162 p = __halves2bfloat162(lo, hi);
    uint32_t u;
    memcpy(&u, &p, 4);
    return u;
}

// ---------------------------------------------------------------------------
// TF32 tensor-core GEMM, double-buffered smem (1 sync / K-step).
// C[M,N] = A[M,K] @ B[K,N] + bias[N], 128x128 block, BK=16, 256 thr / 8 warps.
// ---------------------------------------------------------------------------
struct GemmSmem {
    float As[2][BM * APAD];
    float Bs[2][BKT * BPAD];
};

__device__ __forceinline__
void gemm_tf32_body(const float* __restrict__ A, const float* __restrict__ B,
                    const float* __restrict__ bias, float* __restrict__ C,
                    int M, int N, int K, GemmSmem& sm)
{
    const int tid  = threadIdx.x;
    const int warp = tid >> 5, lane = tid & 31;
    const int g = lane >> 2, t = lane & 3;
    const int wm = (warp >> 2) * 64;
    const int wn = (warp & 3) * 32;

    const int bx = blockIdx.x, by = blockIdx.y;
    const float* Ab = A + (size_t)by * BM * K;
    const float* Bb = B + bx * BN;

    const int arow = tid >> 1, acol = (tid & 1) * 8;
    const int brow = tid >> 4, bcol = (tid & 15) * 8;

    float4 pa0 = *(const float4*)(Ab + (size_t)arow * K + acol);
    float4 pa1 = *(const float4*)(Ab + (size_t)arow * K + acol + 4);
    float4 pb0 = *(const float4*)(Bb + (size_t)brow * N + bcol);
    float4 pb1 = *(const float4*)(Bb + (size_t)brow * N + bcol + 4);

    // commit stage 0
    {
        float* ad = sm.As[0] + arow * APAD + acol;
        ad[0] = tf32r(pa0.x); ad[1] = tf32r(pa0.y); ad[2] = tf32r(pa0.z); ad[3] = tf32r(pa0.w);
        ad[4] = tf32r(pa1.x); ad[5] = tf32r(pa1.y); ad[6] = tf32r(pa1.z); ad[7] = tf32r(pa1.w);
        float* bd = sm.Bs[0] + brow * BPAD + bcol;
        bd[0] = tf32r(pb0.x); bd[1] = tf32r(pb0.y); bd[2] = tf32r(pb0.z); bd[3] = tf32r(pb0.w);
        bd[4] = tf32r(pb1.x); bd[5] = tf32r(pb1.y); bd[6] = tf32r(pb1.z); bd[7] = tf32r(pb1.w);
    }
    __syncthreads();

    float acc[4][4][4];
#pragma unroll
    for (int mt = 0; mt < 4; mt++)
#pragma unroll
        for (int nt = 0; nt < 4; nt++)
#pragma unroll
            for (int i = 0; i < 4; i++) acc[mt][nt][i] = 0.f;

    int buf = 0;
    for (int k0 = 0; k0 < K; k0 += BKT) {
        const bool more = (k0 + BKT) < K;
        if (more) {
            pa0 = *(const float4*)(Ab + (size_t)arow * K + k0 + BKT + acol);
            pa1 = *(const float4*)(Ab + (size_t)arow * K + k0 + BKT + acol + 4);
            pb0 = *(const float4*)(Bb + (size_t)(k0 + BKT + brow) * N + bcol);
            pb1 = *(const float4*)(Bb + (size_t)(k0 + BKT + brow) * N + bcol + 4);
        }

        const float* Asb = sm.As[buf];
        const float* Bsb = sm.Bs[buf];
#pragma unroll
        for (int kk = 0; kk < BKT; kk += 8) {
            uint32_t af[4][4];
#pragma unroll
            for (int mt = 0; mt < 4; mt++) {
                const float* ap = Asb + (wm + mt * 16 + g) * APAD + kk + t;
                af[mt][0] = __float_as_uint(ap[0]);
                af[mt][1] = __float_as_uint(ap[8 * APAD]);
                af[mt][2] = __float_as_uint(ap[4]);
                af[mt][3] = __float_as_uint(ap[8 * APAD + 4]);
            }
            uint32_t bf[4][2];
#pragma unroll
            for (int nt = 0; nt < 4; nt++) {
                const float* bp = Bsb + (kk + t) * BPAD + wn + nt * 8 + g;
                bf[nt][0] = __float_as_uint(bp[0]);
                bf[nt][1] = __float_as_uint(bp[4 * BPAD]);
            }
#pragma unroll
            for (int mt = 0; mt < 4; mt++)
#pragma unroll
                for (int nt = 0; nt < 4; nt++)
                    mma_tf32(acc[mt][nt], af[mt], bf[nt]);
        }

        if (more) {
            float* ad = sm.As[buf ^ 1] + arow * APAD + acol;
            ad[0] = tf32r(pa0.x); ad[1] = tf32r(pa0.y); ad[2] = tf32r(pa0.z); ad[3] = tf32r(pa0.w);
            ad[4] = tf32r(pa1.x); ad[5] = tf32r(pa1.y); ad[6] = tf32r(pa1.z); ad[7] = tf32r(pa1.w);
            float* bd = sm.Bs[buf ^ 1] + brow * BPAD + bcol;
            bd[0] = tf32r(pb0.x); bd[1] = tf32r(pb0.y); bd[2] = tf32r(pb0.z); bd[3] = tf32r(pb0.w);
            bd[4] = tf32r(pb1.x); bd[5] = tf32r(pb1.y); bd[6] = tf32r(pb1.z); bd[7] = tf32r(pb1.w);
        }
        __syncthreads();
        buf ^= 1;
    }

#pragma unroll
    for (int mt = 0; mt < 4; mt++) {
        int row0 = by * BM + wm + mt * 16 + g;
#pragma unroll
        for (int nt = 0; nt < 4; nt++) {
            int col = bx * BN + wn + nt * 8 + 2 * t;
            float b0 = bias[col], b1 = bias[col + 1];
            float2 r0 = make_float2(acc[mt][nt][0] + b0, acc[mt][nt][1] + b1);
            float2 r1 = make_float2(acc[mt][nt][2] + b0, acc[mt][nt][3] + b1);
            *(float2*)(C + (size_t)row0 * N + col) = r0;
            *(float2*)(C + (size_t)(row0 + 8) * N + col) = r1;
        }
    }
}

// Fused Q/K/V projection: blockIdx.z selects which of the 3 GEMMs.
__global__ __launch_bounds__(256, 2)
void gemm_qkv_kernel(const float* __restrict__ q, const float* __restrict__ k,
                     const float* __restrict__ v,
                     const float* __restrict__ Wq, const float* __restrict__ Wk,
                     const float* __restrict__ Wv,
                     const float* __restrict__ bq, const float* __restrict__ bk,
                     const float* __restrict__ bv,
                     float* __restrict__ Cq, float* __restrict__ Ck,
                     float* __restrict__ Cv)
{
    __shared__ GemmSmem sm;
    const int z = blockIdx.z;
    const float* A = (z == 0) ? q : (z == 1) ? k : v;
    const float* B = (z == 0) ? Wq : (z == 1) ? Wk : Wv;
    const float* bias = (z == 0) ? bq : (z == 1) ? bk : bv;
    float* C = (z == 0) ? Cq : (z == 1) ? Ck : Cv;
    gemm_tf32_body(A, B, bias, C, NTOK, D_MODEL, D_MODEL, sm);
}

__global__ __launch_bounds__(256, 2)
void gemm_single_kernel(const float* __restrict__ A, const float* __restrict__ B,
                        const float* __restrict__ bias, float* __restrict__ C)
{
    __shared__ GemmSmem sm;
    gemm_tf32_body(A, B, bias, C, NTOK, D_MODEL, D_MODEL, sm);
}

// ---------------------------------------------------------------------------
// Flash attention, bf16x3 split MMA (proven R6 version: scalar LDS fragments,
// P in registers, Q fragments hoisted). smem = 6 planes * 64*72*2 = 55296 B.
// ---------------------------------------------------------------------------
#define OFF_QH 0
#define OFF_QL (64 * PB)
#define OFF_KH (2 * 64 * PB)
#define OFF_KL (3 * 64 * PB)
#define OFF_VH (4 * 64 * PB)
#define OFF_VL (5 * 64 * PB)
#define ATT_SMEM (6 * 64 * PB * 2)   // 55296 bytes

__global__ __launch_bounds__(128, 3)
void attention_bf16x3_kernel(const float* __restrict__ Q, const float* __restrict__ K,
                             const float* __restrict__ V, float* __restrict__ O)
{
    extern __shared__ __align__(16) __nv_bfloat16 sb[];
    __nv_bfloat16* Qh = sb + OFF_QH;
    __nv_bfloat16* Ql = sb + OFF_QL;
    __nv_bfloat16* Kh = sb + OFF_KH;
    __nv_bfloat16* Kl = sb + OFF_KL;
    __nv_bfloat16* Vh = sb + OFF_VH;   // transposed [d][key]
    __nv_bfloat16* Vl = sb + OFF_VL;

    const uint32_t* Qh32 = (const uint32_t*)Qh;
    const uint32_t* Ql32 = (const uint32_t*)Ql;
    const uint32_t* Kh32 = (const uint32_t*)Kh;
    const uint32_t* Kl32 = (const uint32_t*)Kl;
    const uint32_t* Vh32 = (const uint32_t*)Vh;
    const uint32_t* Vl32 = (const uint32_t*)Vl;

    const int tid  = threadIdx.x;
    const int warp = tid >> 5, lane = tid & 31;
    const int g = lane >> 2, t = lane & 3;
    const int row16 = warp * 16;

    const int qt = blockIdx.x, h = blockIdx.y, b = blockIdx.z;
    const size_t base = ((size_t)b * TSEQ) * D_MODEL + (size_t)h * HD;
    const float* Qb = Q + base + (size_t)qt * 64 * D_MODEL;
    const float* Kb = K + base;
    const float* Vb = V + base;

    // ---- Load + scale + split Q once (64x64) ----
#pragma unroll
    for (int it = 0; it < 8; it++) {
        int i = tid + it * 128;
        int r = i >> 4, c = (i & 15) * 4;
        float4 q4 = *(const float4*)(Qb + (size_t)r * D_MODEL + c);
        __nv_bfloat16 h0, h1, h2, h3, l0, l1, l2, l3;
        bsplit(q4.x * 0.125f, h0, l0); bsplit(q4.y * 0.125f, h1, l1);
        bsplit(q4.z * 0.125f, h2, l2); bsplit(q4.w * 0.125f, h3, l3);
        *(uint32_t*)&Qh[r * PB + c]     = pack2(h0, h1);
        *(uint32_t*)&Qh[r * PB + c + 2] = pack2(h2, h3);
        *(uint32_t*)&Ql[r * PB + c]     = pack2(l0, l1);
        *(uint32_t*)&Ql[r * PB + c + 2] = pack2(l2, l3);
    }
    __syncthreads();

    // ---- Hoist Q fragments to registers (loop-invariant) ----
    uint32_t qfh[4][4], qfl[4][4];
#pragma unroll
    for (int u = 0; u < 4; u++) {
        const int w0 = u * 8 + t;
        qfh[u][0] = Qh32[(row16 + g) * PB32 + w0];
        qfh[u][1] = Qh32[(row16 + g + 8) * PB32 + w0];
        qfh[u][2] = Qh32[(row16 + g) * PB32 + w0 + 4];
        qfh[u][3] = Qh32[(row16 + g + 8) * PB32 + w0 + 4];
        qfl[u][0] = Ql32[(row16 + g) * PB32 + w0];
        qfl[u][1] = Ql32[(row16 + g + 8) * PB32 + w0];
        qfl[u][2] = Ql32[(row16 + g) * PB32 + w0 + 4];
        qfl[u][3] = Ql32[(row16 + g + 8) * PB32 + w0 + 4];
    }

    float oacc[8][4];
#pragma unroll
    for (int j = 0; j < 8; j++)
#pragma unroll
        for (int i = 0; i < 4; i++) oacc[j][i] = 0.f;
    float m0 = -1e30f, m1 = -1e30f, l0s = 0.f, l1s = 0.f;

    const int vrow = row16 + (lane & 15);
    const int vcg  = lane >> 4;

    for (int j0 = 0; j0 < TSEQ; j0 += 64) {
        __syncthreads();  // previous tile's K/V reads complete

        // ---- Load + split K (coalesced), V (transposed) ----
#pragma unroll
        for (int it = 0; it < 8; it++) {
            int i = tid + it * 128;
            int r = i >> 4, c = (i & 15) * 4;
            float4 k4 = *(const float4*)(Kb + (size_t)(j0 + r) * D_MODEL + c);
            __nv_bfloat16 h0, h1, h2, h3, l0, l1, l2, l3;
            bsplit(k4.x, h0, l0); bsplit(k4.y, h1, l1);
            bsplit(k4.z, h2, l2); bsplit(k4.w, h3, l3);
            *(uint32_t*)&Kh[r * PB + c]     = pack2(h0, h1);
            *(uint32_t*)&Kh[r * PB + c + 2] = pack2(h2, h3);
            *(uint32_t*)&Kl[r * PB + c]     = pack2(l0, l1);
            *(uint32_t*)&Kl[r * PB + c + 2] = pack2(l2, l3);
        }
#pragma unroll
        for (int it = 0; it < 8; it++) {
            int c = (vcg + 2 * it) * 4;
            float4 v4 = *(const float4*)(Vb + (size_t)(j0 + vrow) * D_MODEL + c);
            __nv_bfloat16 hh, ll;
            bsplit(v4.x, hh, ll); Vh[(c + 0) * PB + vrow] = hh; Vl[(c + 0) * PB + vrow] = ll;
            bsplit(v4.y, hh, ll); Vh[(c + 1) * PB + vrow] = hh; Vl[(c + 1) * PB + vrow] = ll;
            bsplit(v4.z, hh, ll); Vh[(c + 2) * PB + vrow] = hh; Vl[(c + 2) * PB + vrow] = ll;
            bsplit(v4.w, hh, ll); Vh[(c + 3) * PB + vrow] = hh; Vl[(c + 3) * PB + vrow] = ll;
        }
        __syncthreads();

        // ---- S = Q K^T  (bf16x3: QhKh + QhKl + QlKh) ----
        float sacc[8][4];
#pragma unroll
        for (int j = 0; j < 8; j++)
#pragma unroll
            for (int i = 0; i < 4; i++) sacc[j][i] = 0.f;

#pragma unroll
        for (int u = 0; u < 4; u++) {
            const int w0 = u * 8 + t;
#pragma unroll
            for (int j = 0; j < 8; j++) {
                uint32_t kh0 = Kh32[(j * 8 + g) * PB32 + w0];
                uint32_t kh1 = Kh32[(j * 8 + g) * PB32 + w0 + 4];
                uint32_t kl0 = Kl32[(j * 8 + g) * PB32 + w0];
                uint32_t kl1 = Kl32[(j * 8 + g) * PB32 + w0 + 4];
                mma_bf16(sacc[j], qfh[u], kh0, kh1);
                mma_bf16(sacc[j], qfh[u], kl0, kl1);
                mma_bf16(sacc[j], qfl[u], kh0, kh1);
            }
        }

        // ---- Online softmax on fragments (rows g and g+8) ----
        float mx0 = -1e30f, mx1 = -1e30f;
#pragma unroll
        for (int j = 0; j < 8; j++) {
            mx0 = fmaxf(mx0, fmaxf(sacc[j][0], sacc[j][1]));
            mx1 = fmaxf(mx1, fmaxf(sacc[j][2], sacc[j][3]));
        }
        mx0 = fmaxf(mx0, __shfl_xor_sync(0xffffffffu, mx0, 1));
        mx0 = fmaxf(mx0, __shfl_xor_sync(0xffffffffu, mx0, 2));
        mx1 = fmaxf(mx1, __shfl_xor_sync(0xffffffffu, mx1, 1));
        mx1 = fmaxf(mx1, __shfl_xor_sync(0xffffffffu, mx1, 2));

        float mn0 = fmaxf(m0, mx0), mn1 = fmaxf(m1, mx1);
        float fac0 = __expf(m0 - mn0), fac1 = __expf(m1 - mn1);
        m0 = mn0; m1 = mn1;

        uint32_t ph01[8], ph23[8], pl01[8], pl23[8];
        float rs0 = 0.f, rs1 = 0.f;
#pragma unroll
        for (int j = 0; j < 8; j++) {
            float p0 = __expf(sacc[j][0] - mn0);
            float p1 = __expf(sacc[j][1] - mn0);
            float p2 = __expf(sacc[j][2] - mn1);
            float p3 = __expf(sacc[j][3] - mn1);
            rs0 += p0 + p1; rs1 += p2 + p3;
            __nv_bfloat16 h0, h1, h2, h3, q0, q1, q2, q3;
            bsplit(p0, h0, q0); bsplit(p1, h1, q1);
            bsplit(p2, h2, q2); bsplit(p3, h3, q3);
            ph01[j] = pack2(h0, h1);
            ph23[j] = pack2(h2, h3);
            pl01[j] = pack2(q0, q1);
            pl23[j] = pack2(q2, q3);
        }
        rs0 += __shfl_xor_sync(0xffffffffu, rs0, 1);
        rs0 += __shfl_xor_sync(0xffffffffu, rs0, 2);
        rs1 += __shfl_xor_sync(0xffffffffu, rs1, 1);
        rs1 += __shfl_xor_sync(0xffffffffu, rs1, 2);
        l0s = l0s * fac0 + rs0;
        l1s = l1s * fac1 + rs1;
#pragma unroll
        for (int j = 0; j < 8; j++) {
            oacc[j][0] *= fac0; oacc[j][1] *= fac0;
            oacc[j][2] *= fac1; oacc[j][3] *= fac1;
        }

        // ---- O += P V  (bf16x3: PhVh + PhVl + PlVh), P from registers ----
#pragma unroll
        for (int u = 0; u < 4; u++) {
            const int w0 = u * 8 + t;
            uint32_t pfh[4] = { ph01[2 * u], ph23[2 * u], ph01[2 * u + 1], ph23[2 * u + 1] };
            uint32_t pfl[4] = { pl01[2 * u], pl23[2 * u], pl01[2 * u + 1], pl23[2 * u + 1] };
#pragma unroll
            for (int j = 0; j < 8; j++) {
                uint32_t vh0 = Vh32[(j * 8 + g) * PB32 + w0];
                uint32_t vh1 = Vh32[(j * 8 + g) * PB32 + w0 + 4];
                uint32_t vl0 = Vl32[(j * 8 + g) * PB32 + w0];
                uint32_t vl1 = Vl32[(j * 8 + g) * PB32 + w0 + 4];
                mma_bf16(oacc[j], pfh, vh0, vh1);
                mma_bf16(oacc[j], pfh, vl0, vl1);
                mma_bf16(oacc[j], pfl, vh0, vh1);
            }
        }
    }

    // ---- Epilogue: normalize, store ----
    float inv0 = 1.f / l0s, inv1 = 1.f / l1s;
    float* Ob = O + base + (size_t)qt * 64 * D_MODEL;
#pragma unroll
    for (int j = 0; j < 8; j++) {
        int col = j * 8 + 2 * t;
        *(float2*)(Ob + (size_t)(row16 + g) * D_MODEL + col) =
            make_float2(oacc[j][0] * inv0, oacc[j][1] * inv0);
        *(float2*)(Ob + (size_t)(row16 + g + 8) * D_MODEL + col) =
            make_float2(oacc[j][2] * inv1, oacc[j][3] * inv1);
    }
}

// ---------------------------------------------------------------------------
// Launch. Input order:
// 0:q 1:k 2:v 3:W_q 4:b_q 5:W_k 6:b_k 7:W_v 8:b_v 9:W_o 10:b_o
// ---------------------------------------------------------------------------
extern "C" void kernel_launch(void* const* d_in, const int* in_sizes, int n_in,
                              void* d_out, int out_size)
{
    (void)in_sizes; (void)n_in; (void)out_size;
    const float* q   = (const float*)d_in[0];
    const float* k   = (const float*)d_in[1];
    const float* v   = (const float*)d_in[2];
    const float* W_q = (const float*)d_in[3];
    const float* b_q = (const float*)d_in[4];
    const float* W_k = (const float*)d_in[5];
    const float* b_k = (const float*)d_in[6];
    const float* W_v = (const float*)d_in[7];
    const float* b_v = (const float*)d_in[8];
    const float* W_o = (const float*)d_in[9];
    const float* b_o = (const float*)d_in[10];
    float* out = (float*)d_out;

    float *gQ, *gK, *gV, *gA;
    cudaGetSymbolAddress((void**)&gQ, g_Q);
    cudaGetSymbolAddress((void**)&gK, g_K);
    cudaGetSymbolAddress((void**)&gV, g_V);
    cudaGetSymbolAddress((void**)&gA, g_A);

    // Fused Q/K/V projections (grid.z selects the GEMM)
    gemm_qkv_kernel<<<dim3(D_MODEL / BN, NTOK / BM, 3), 256>>>(
        q, k, v, W_q, W_k, W_v, b_q, b_k, b_v, gQ, gK, gV);

    cudaFuncSetAttribute(attention_bf16x3_kernel,
                         cudaFuncAttributeMaxDynamicSharedMemorySize, ATT_SMEM);
    attention_bf16x3_kernel<<<dim3(TSEQ / 64, HEADS, BATCH), 128, ATT_SMEM>>>(gQ, gK, gV, gA);

    gemm_single_kernel<<<dim3(D_MODEL / BN, NTOK / BM), 256>>>(gA, W_o, b_o, out);
}

// round 10
// speedup vs baseline: 1.8875x; 1.6308x over previous
#include <cuda_runtime.h>
#include <cuda_fp16.h>
#include <math.h>
#include <stdint.h>
#include <string.h>

#define D_MODEL 1024
#define NTOK    8192   // B*T
#define HEADS   16
#define HD      64
#define TSEQ    2048
#define BATCH   4

// GEMM tiling
#define BM 128
#define BN 128
#define BKT 16
#define APAD 20
#define BPAD 136

// Attention fp16 smem pitch (fp16 elements). 72*2B=144B rows; 36 words.
#define PB   72
#define PB32 36

// Scratch (no allocation allowed — device globals). 16B-aligned.
__device__ __align__(16) float g_Q[NTOK * D_MODEL];
__device__ __align__(16) float g_K[NTOK * D_MODEL];
__device__ __align__(16) float g_V[NTOK * D_MODEL];
__device__ __align__(16) float g_A[NTOK * D_MODEL];

__device__ __forceinline__ float tf32r(float x) {
    uint32_t u;
    asm("cvt.rna.tf32.f32 %0, %1;" : "=r"(u) : "f"(x));
    return __uint_as_float(u);
}

__device__ __forceinline__ void mma_tf32(float* c, const uint32_t* a, const uint32_t* b) {
    asm volatile(
        "mma.sync.aligned.m16n8k8.row.col.f32.tf32.tf32.f32 "
        "{%0,%1,%2,%3}, {%4,%5,%6,%7}, {%8,%9}, {%0,%1,%2,%3};\n"
        : "+f"(c[0]), "+f"(c[1]), "+f"(c[2]), "+f"(c[3])
        : "r"(a[0]), "r"(a[1]), "r"(a[2]), "r"(a[3]), "r"(b[0]), "r"(b[1]));
}

__device__ __forceinline__ void mma_f16(float* c, const uint32_t* a, uint32_t b0, uint32_t b1) {
    asm volatile(
        "mma.sync.aligned.m16n8k16.row.col.f32.f16.f16.f32 "
        "{%0,%1,%2,%3}, {%4,%5,%6,%7}, {%8,%9}, {%0,%1,%2,%3};\n"
        : "+f"(c[0]), "+f"(c[1]), "+f"(c[2]), "+f"(c[3])
        : "r"(a[0]), "r"(a[1]), "r"(a[2]), "r"(a[3]), "r"(b0), "r"(b1));
}

// split fp32 -> fp16 hi + fp16 lo (hi+lo reproduces ~22 mantissa bits)
__device__ __forceinline__ void hsplit(float x, __half& h, __half& l) {
    h = __float2half_rn(x);
    l = __float2half_rn(x - __half2float(h));
}

// pack two fp16 into one 32-bit word (lo -> low half)
__device__ __forceinline__ uint32_t pack2h(__half lo, __half hi) {
    __half2 p = __halves2half2(lo, hi);
    uint32_t u;
    memcpy(&u, &p, 4);
    return u;
}

// ---------------------------------------------------------------------------
// TF32 tensor-core GEMM — exact R7-proven single-buffer version.
// ---------------------------------------------------------------------------
__global__ __launch_bounds__(256, 2)
void gemm_tf32_bias(const float* __restrict__ A, const float* __restrict__ B,
                    const float* __restrict__ bias, float* __restrict__ C,
                    int M, int N, int K)
{
    __shared__ float As[BM * APAD];
    __shared__ float Bs[BKT * BPAD];

    const int tid  = threadIdx.x;
    const int warp = tid >> 5, lane = tid & 31;
    const int g = lane >> 2, t = lane & 3;
    const int wm = (warp >> 2) * 64;
    const int wn = (warp & 3) * 32;

    const int bx = blockIdx.x, by = blockIdx.y;
    const float* Ab = A + (size_t)by * BM * K;
    const float* Bb = B + bx * BN;

    const int arow = tid >> 1, acol = (tid & 1) * 8;
    const int brow = tid >> 4, bcol = (tid & 15) * 8;

    float4 pa0 = *(const float4*)(Ab + (size_t)arow * K + acol);
    float4 pa1 = *(const float4*)(Ab + (size_t)arow * K + acol + 4);
    float4 pb0 = *(const float4*)(Bb + (size_t)brow * N + bcol);
    float4 pb1 = *(const float4*)(Bb + (size_t)brow * N + bcol + 4);

    float acc[4][4][4];
#pragma unroll
    for (int mt = 0; mt < 4; mt++)
#pragma unroll
        for (int nt = 0; nt < 4; nt++)
#pragma unroll
            for (int i = 0; i < 4; i++) acc[mt][nt][i] = 0.f;

    for (int k0 = 0; k0 < K; k0 += BKT) {
        float* ad = As + arow * APAD + acol;
        ad[0] = tf32r(pa0.x); ad[1] = tf32r(pa0.y); ad[2] = tf32r(pa0.z); ad[3] = tf32r(pa0.w);
        ad[4] = tf32r(pa1.x); ad[5] = tf32r(pa1.y); ad[6] = tf32r(pa1.z); ad[7] = tf32r(pa1.w);
        float* bd = Bs + brow * BPAD + bcol;
        bd[0] = tf32r(pb0.x); bd[1] = tf32r(pb0.y); bd[2] = tf32r(pb0.z); bd[3] = tf32r(pb0.w);
        bd[4] = tf32r(pb1.x); bd[5] = tf32r(pb1.y); bd[6] = tf32r(pb1.z); bd[7] = tf32r(pb1.w);
        __syncthreads();

        if (k0 + BKT < K) {
            pa0 = *(const float4*)(Ab + (size_t)arow * K + k0 + BKT + acol);
            pa1 = *(const float4*)(Ab + (size_t)arow * K + k0 + BKT + acol + 4);
            pb0 = *(const float4*)(Bb + (size_t)(k0 + BKT + brow) * N + bcol);
            pb1 = *(const float4*)(Bb + (size_t)(k0 + BKT + brow) * N + bcol + 4);
        }

#pragma unroll
        for (int kk = 0; kk < BKT; kk += 8) {
            uint32_t af[4][4];
#pragma unroll
            for (int mt = 0; mt < 4; mt++) {
                const float* ap = As + (wm + mt * 16 + g) * APAD + kk + t;
                af[mt][0] = __float_as_uint(ap[0]);
                af[mt][1] = __float_as_uint(ap[8 * APAD]);
                af[mt][2] = __float_as_uint(ap[4]);
                af[mt][3] = __float_as_uint(ap[8 * APAD + 4]);
            }
            uint32_t bf[4][2];
#pragma unroll
            for (int nt = 0; nt < 4; nt++) {
                const float* bp = Bs + (kk + t) * BPAD + wn + nt * 8 + g;
                bf[nt][0] = __float_as_uint(bp[0]);
                bf[nt][1] = __float_as_uint(bp[4 * BPAD]);
            }
#pragma unroll
            for (int mt = 0; mt < 4; mt++)
#pragma unroll
                for (int nt = 0; nt < 4; nt++)
                    mma_tf32(acc[mt][nt], af[mt], bf[nt]);
        }
        __syncthreads();
    }

#pragma unroll
    for (int mt = 0; mt < 4; mt++) {
        int row0 = by * BM + wm + mt * 16 + g;
#pragma unroll
        for (int nt = 0; nt < 4; nt++) {
            int col = bx * BN + wn + nt * 8 + 2 * t;
            float b0 = bias[col], b1 = bias[col + 1];
            float2 r0 = make_float2(acc[mt][nt][0] + b0, acc[mt][nt][1] + b1);
            float2 r1 = make_float2(acc[mt][nt][2] + b0, acc[mt][nt][3] + b1);
            *(float2*)(C + (size_t)row0 * N + col) = r0;
            *(float2*)(C + (size_t)(row0 + 8) * N + col) = r1;
        }
    }
}

// ---------------------------------------------------------------------------
// Flash attention, fp16 A-side-split MMA. Q and P split into fp16 hi+lo
// (A-side effectively exact); K and V stored fp16 hi only. S = (Qh+Ql)Kh via
// 2 MMAs; O += (Ph+Pl)Vh via 2 MMAs. Structure identical to the proven R6
// kernel: scalar LDS fragments, P in registers, Q fragments hoisted.
// smem planes (pitch PB=72 fp16): Qh Ql Kh Vth = 4*64*72*2 = 36864 B.
// ---------------------------------------------------------------------------
#define OFF_QH 0
#define OFF_QL (64 * PB)
#define OFF_KH (2 * 64 * PB)
#define OFF_VH (3 * 64 * PB)
#define ATT_SMEM (4 * 64 * PB * 2)   // 36864 bytes

__global__ __launch_bounds__(128, 3)
void attention_f16_kernel(const float* __restrict__ Q, const float* __restrict__ K,
                          const float* __restrict__ V, float* __restrict__ O)
{
    extern __shared__ __align__(16) __half sh[];
    __half* Qh = sh + OFF_QH;
    __half* Ql = sh + OFF_QL;
    __half* Kh = sh + OFF_KH;
    __half* Vh = sh + OFF_VH;   // transposed [d][key]

    const uint32_t* Qh32 = (const uint32_t*)Qh;
    const uint32_t* Ql32 = (const uint32_t*)Ql;
    const uint32_t* Kh32 = (const uint32_t*)Kh;
    const uint32_t* Vh32 = (const uint32_t*)Vh;

    const int tid  = threadIdx.x;
    const int warp = tid >> 5, lane = tid & 31;
    const int g = lane >> 2, t = lane & 3;
    const int row16 = warp * 16;

    const int qt = blockIdx.x, h = blockIdx.y, b = blockIdx.z;
    const size_t base = ((size_t)b * TSEQ) * D_MODEL + (size_t)h * HD;
    const float* Qb = Q + base + (size_t)qt * 64 * D_MODEL;
    const float* Kb = K + base;
    const float* Vb = V + base;

    // ---- Load + scale + split Q once (64x64) ----
#pragma unroll
    for (int it = 0; it < 8; it++) {
        int i = tid + it * 128;
        int r = i >> 4, c = (i & 15) * 4;
        float4 q4 = *(const float4*)(Qb + (size_t)r * D_MODEL + c);
        __half h0, h1, h2, h3, l0, l1, l2, l3;
        hsplit(q4.x * 0.125f, h0, l0); hsplit(q4.y * 0.125f, h1, l1);
        hsplit(q4.z * 0.125f, h2, l2); hsplit(q4.w * 0.125f, h3, l3);
        *(uint32_t*)&Qh[r * PB + c]     = pack2h(h0, h1);
        *(uint32_t*)&Qh[r * PB + c + 2] = pack2h(h2, h3);
        *(uint32_t*)&Ql[r * PB + c]     = pack2h(l0, l1);
        *(uint32_t*)&Ql[r * PB + c + 2] = pack2h(l2, l3);
    }
    __syncthreads();

    // ---- Hoist Q fragments to registers (loop-invariant) ----
    uint32_t qfh[4][4], qfl[4][4];
#pragma unroll
    for (int u = 0; u < 4; u++) {
        const int w0 = u * 8 + t;
        qfh[u][0] = Qh32[(row16 + g) * PB32 + w0];
        qfh[u][1] = Qh32[(row16 + g + 8) * PB32 + w0];
        qfh[u][2] = Qh32[(row16 + g) * PB32 + w0 + 4];
        qfh[u][3] = Qh32[(row16 + g + 8) * PB32 + w0 + 4];
        qfl[u][0] = Ql32[(row16 + g) * PB32 + w0];
        qfl[u][1] = Ql32[(row16 + g + 8) * PB32 + w0];
        qfl[u][2] = Ql32[(row16 + g) * PB32 + w0 + 4];
        qfl[u][3] = Ql32[(row16 + g + 8) * PB32 + w0 + 4];
    }

    float oacc[8][4];
#pragma unroll
    for (int j = 0; j < 8; j++)
#pragma unroll
        for (int i = 0; i < 4; i++) oacc[j][i] = 0.f;
    float m0 = -1e30f, m1 = -1e30f, l0s = 0.f, l1s = 0.f;

    const int vrow = row16 + (lane & 15);
    const int vcg  = lane >> 4;

    for (int j0 = 0; j0 < TSEQ; j0 += 64) {
        __syncthreads();  // previous tile's K/V reads complete

        // ---- Load K (coalesced, fp16 hi), V (transposed, fp16 hi) ----
#pragma unroll
        for (int it = 0; it < 8; it++) {
            int i = tid + it * 128;
            int r = i >> 4, c = (i & 15) * 4;
            float4 k4 = *(const float4*)(Kb + (size_t)(j0 + r) * D_MODEL + c);
            *(uint32_t*)&Kh[r * PB + c]     = pack2h(__float2half_rn(k4.x), __float2half_rn(k4.y));
            *(uint32_t*)&Kh[r * PB + c + 2] = pack2h(__float2half_rn(k4.z), __float2half_rn(k4.w));
        }
#pragma unroll
        for (int it = 0; it < 8; it++) {
            int c = (vcg + 2 * it) * 4;
            float4 v4 = *(const float4*)(Vb + (size_t)(j0 + vrow) * D_MODEL + c);
            Vh[(c + 0) * PB + vrow] = __float2half_rn(v4.x);
            Vh[(c + 1) * PB + vrow] = __float2half_rn(v4.y);
            Vh[(c + 2) * PB + vrow] = __float2half_rn(v4.z);
            Vh[(c + 3) * PB + vrow] = __float2half_rn(v4.w);
        }
        __syncthreads();

        // ---- S = (Qh + Ql) Kh^T  (2 MMAs per subtile) ----
        float sacc[8][4];
#pragma unroll
        for (int j = 0; j < 8; j++)
#pragma unroll
            for (int i = 0; i < 4; i++) sacc[j][i] = 0.f;

#pragma unroll
        for (int u = 0; u < 4; u++) {
            const int w0 = u * 8 + t;
#pragma unroll
            for (int j = 0; j < 8; j++) {
                uint32_t kh0 = Kh32[(j * 8 + g) * PB32 + w0];
                uint32_t kh1 = Kh32[(j * 8 + g) * PB32 + w0 + 4];
                mma_f16(sacc[j], qfh[u], kh0, kh1);
                mma_f16(sacc[j], qfl[u], kh0, kh1);
            }
        }

        // ---- Online softmax on fragments (rows g and g+8) ----
        float mx0 = -1e30f, mx1 = -1e30f;
#pragma unroll
        for (int j = 0; j < 8; j++) {
            mx0 = fmaxf(mx0, fmaxf(sacc[j][0], sacc[j][1]));
            mx1 = fmaxf(mx1, fmaxf(sacc[j][2], sacc[j][3]));
        }
        mx0 = fmaxf(mx0, __shfl_xor_sync(0xffffffffu, mx0, 1));
        mx0 = fmaxf(mx0, __shfl_xor_sync(0xffffffffu, mx0, 2));
        mx1 = fmaxf(mx1, __shfl_xor_sync(0xffffffffu, mx1, 1));
        mx1 = fmaxf(mx1, __shfl_xor_sync(0xffffffffu, mx1, 2));

        float mn0 = fmaxf(m0, mx0), mn1 = fmaxf(m1, mx1);
        float fac0 = __expf(m0 - mn0), fac1 = __expf(m1 - mn1);
        m0 = mn0; m1 = mn1;

        uint32_t ph01[8], ph23[8], pl01[8], pl23[8];
        float rs0 = 0.f, rs1 = 0.f;
#pragma unroll
        for (int j = 0; j < 8; j++) {
            float p0 = __expf(sacc[j][0] - mn0);
            float p1 = __expf(sacc[j][1] - mn0);
            float p2 = __expf(sacc[j][2] - mn1);
            float p3 = __expf(sacc[j][3] - mn1);
            rs0 += p0 + p1; rs1 += p2 + p3;
            __half h0, h1, h2, h3, q0, q1, q2, q3;
            hsplit(p0, h0, q0); hsplit(p1, h1, q1);
            hsplit(p2, h2, q2); hsplit(p3, h3, q3);
            ph01[j] = pack2h(h0, h1);
            ph23[j] = pack2h(h2, h3);
            pl01[j] = pack2h(q0, q1);
            pl23[j] = pack2h(q2, q3);
        }
        rs0 += __shfl_xor_sync(0xffffffffu, rs0, 1);
        rs0 += __shfl_xor_sync(0xffffffffu, rs0, 2);
        rs1 += __shfl_xor_sync(0xffffffffu, rs1, 1);
        rs1 += __shfl_xor_sync(0xffffffffu, rs1, 2);
        l0s = l0s * fac0 + rs0;
        l1s = l1s * fac1 + rs1;
#pragma unroll
        for (int j = 0; j < 8; j++) {
            oacc[j][0] *= fac0; oacc[j][1] *= fac0;
            oacc[j][2] *= fac1; oacc[j][3] *= fac1;
        }

        // ---- O += (Ph + Pl) Vh  (2 MMAs per subtile), P from registers ----
#pragma unroll
        for (int u = 0; u < 4; u++) {
            const int w0 = u * 8 + t;
            uint32_t pfh[4] = { ph01[2 * u], ph23[2 * u], ph01[2 * u + 1], ph23[2 * u + 1] };
            uint32_t pfl[4] = { pl01[2 * u], pl23[2 * u], pl01[2 * u + 1], pl23[2 * u + 1] };
#pragma unroll
            for (int j = 0; j < 8; j++) {
                uint32_t vh0 = Vh32[(j * 8 + g) * PB32 + w0];
                uint32_t vh1 = Vh32[(j * 8 + g) * PB32 + w0 + 4];
                mma_f16(oacc[j], pfh, vh0, vh1);
                mma_f16(oacc[j], pfl, vh0, vh1);
            }
        }
    }

    // ---- Epilogue: normalize, store ----
    float inv0 = 1.f / l0s, inv1 = 1.f / l1s;
    float* Ob = O + base + (size_t)qt * 64 * D_MODEL;
#pragma unroll
    for (int j = 0; j < 8; j++) {
        int col = j * 8 + 2 * t;
        *(float2*)(Ob + (size_t)(row16 + g) * D_MODEL + col) =
            make_float2(oacc[j][0] * inv0, oacc[j][1] * inv0);
        *(float2*)(Ob + (size_t)(row16 + g + 8) * D_MODEL + col) =
            make_float2(oacc[j][2] * inv1, oacc[j][3] * inv1);
    }
}

// ---------------------------------------------------------------------------
// Launch. Input order:
// 0:q 1:k 2:v 3:W_q 4:b_q 5:W_k 6:b_k 7:W_v 8:b_v 9:W_o 10:b_o
// ---------------------------------------------------------------------------
extern "C" void kernel_launch(void* const* d_in, const int* in_sizes, int n_in,
                              void* d_out, int out_size)
{
    (void)in_sizes; (void)n_in; (void)out_size;
    const float* q   = (const float*)d_in[0];
    const float* k   = (const float*)d_in[1];
    const float* v   = (const float*)d_in[2];
    const float* W_q = (const float*)d_in[3];
    const float* b_q = (const float*)d_in[4];
    const float* W_k = (const float*)d_in[5];
    const float* b_k = (const float*)d_in[6];
    const float* W_v = (const float*)d_in[7];
    const float* b_v = (const float*)d_in[8];
    const float* W_o = (const float*)d_in[9];
    const float* b_o = (const float*)d_in[10];
    float* out = (float*)d_out;

    float *gQ, *gK, *gV, *gA;
    cudaGetSymbolAddress((void**)&gQ, g_Q);
    cudaGetSymbolAddress((void**)&gK, g_K);
    cudaGetSymbolAddress((void**)&gV, g_V);
    cudaGetSymbolAddress((void**)&gA, g_A);

    dim3 gridP(D_MODEL / BN, NTOK / BM);  // (8, 64)

    gemm_tf32_bias<<<gridP, 256>>>(q, W_q, b_q, gQ, NTOK, D_MODEL, D_MODEL);
    gemm_tf32_bias<<<gridP, 256>>>(k, W_k, b_k, gK, NTOK, D_MODEL, D_MODEL);
    gemm_tf32_bias<<<gridP, 256>>>(v, W_v, b_v, gV, NTOK, D_MODEL, D_MODEL);

    cudaFuncSetAttribute(attention_f16_kernel,
                         cudaFuncAttributeMaxDynamicSharedMemorySize, ATT_SMEM);
    attention_f16_kernel<<<dim3(TSEQ / 64, HEADS, BATCH), 128, ATT_SMEM>>>(gQ, gK, gV, gA);

    gemm_tf32_bias<<<gridP, 256>>>(gA, W_o, b_o, out, NTOK, D_MODEL, D_MODEL);
}